// round 1
// baseline (speedup 1.0000x reference)
#include <cuda_runtime.h>
#include <cuda_bf16.h>

// Problem: softmask [B=16, K=64, H=240, W=320] fp32.
// out = sqrt( sum over 1024 slices of unbiased variance over H*W=76800 elems )
//
// Kernel 1: one CTA per slice -> per-slice variance into __device__ scratch.
// Kernel 2: one CTA reduces 1024 variances, sqrt, writes scalar.

#define HW        76800          // 240*320
#define HW4       (HW / 4)       // 19200 float4 per slice
#define NSLICES   1024           // 16*64
#define NTHREADS  256

__device__ float g_slice_var[NSLICES];

__global__ __launch_bounds__(NTHREADS)
void slice_var_kernel(const float4* __restrict__ in) {
    const int s = blockIdx.x;
    const float4* __restrict__ p = in + (size_t)s * HW4;

    float sum = 0.f, sq = 0.f;

    // 19200 / 256 = 75 iterations per thread; unroll for MLP.
    #pragma unroll 5
    for (int i = threadIdx.x; i < HW4; i += NTHREADS) {
        float4 v = p[i];
        sum += (v.x + v.y) + (v.z + v.w);
        sq  += (v.x * v.x + v.y * v.y) + (v.z * v.z + v.w * v.w);
    }

    // warp reduce
    #pragma unroll
    for (int off = 16; off > 0; off >>= 1) {
        sum += __shfl_xor_sync(0xffffffffu, sum, off);
        sq  += __shfl_xor_sync(0xffffffffu, sq,  off);
    }

    __shared__ float s_sum[NTHREADS / 32];
    __shared__ float s_sq [NTHREADS / 32];
    const int lane = threadIdx.x & 31;
    const int wid  = threadIdx.x >> 5;
    if (lane == 0) { s_sum[wid] = sum; s_sq[wid] = sq; }
    __syncthreads();

    if (wid == 0) {
        sum = (lane < NTHREADS / 32) ? s_sum[lane] : 0.f;
        sq  = (lane < NTHREADS / 32) ? s_sq [lane] : 0.f;
        #pragma unroll
        for (int off = 4; off > 0; off >>= 1) {
            sum += __shfl_xor_sync(0xffffffffu, sum, off);
            sq  += __shfl_xor_sync(0xffffffffu, sq,  off);
        }
        if (lane == 0) {
            // unbiased: (sumsq - sum^2/n) / (n-1)
            float var = (sq - sum * sum * (1.0f / (float)HW)) * (1.0f / (float)(HW - 1));
            g_slice_var[s] = var;
        }
    }
}

__global__ __launch_bounds__(NTHREADS)
void final_reduce_kernel(float* __restrict__ out) {
    float acc = 0.f;
    for (int i = threadIdx.x; i < NSLICES; i += NTHREADS)
        acc += g_slice_var[i];

    #pragma unroll
    for (int off = 16; off > 0; off >>= 1)
        acc += __shfl_xor_sync(0xffffffffu, acc, off);

    __shared__ float s_acc[NTHREADS / 32];
    const int lane = threadIdx.x & 31;
    const int wid  = threadIdx.x >> 5;
    if (lane == 0) s_acc[wid] = acc;
    __syncthreads();

    if (threadIdx.x == 0) {
        float t = 0.f;
        #pragma unroll
        for (int w = 0; w < NTHREADS / 32; w++) t += s_acc[w];
        out[0] = sqrtf(t);
    }
}

extern "C" void kernel_launch(void* const* d_in, const int* in_sizes, int n_in,
                              void* d_out, int out_size) {
    const float4* in = (const float4*)d_in[0];
    float* out = (float*)d_out;

    slice_var_kernel<<<NSLICES, NTHREADS>>>(in);
    final_reduce_kernel<<<1, NTHREADS>>>(out);
}